// round 6
// baseline (speedup 1.0000x reference)
#include <cuda_runtime.h>
#include <cuda_bf16.h>
#include <stdint.h>

#define NNODES 8192
#define DIM    256
#define ALPHA  3.0f
#define NEG    0.2f

#define TPB  256                 // softmax threads per block (proven shape)
#define CPT  (NNODES / TPB)      // 32 columns per thread
#define G4   (CPT / 4)           // 8 groups of 4 columns

// Scratch (__device__ globals; no cudaMalloc allowed)
// g_row[i] = ( e^{s1[i]+b},  e^{0.2*(s1[i]+b)} )
// g_col[c] = ( e^{s2p[c]},   e^{0.2*s2p[c]} )   with s2p[idx[j]] = s2[j]
__device__ float2 g_row[NNODES];
__device__ float2 g_col[NNODES];

__device__ __forceinline__ float fast_tanh_alpha(float v) {
    // tanh(ALPHA*v) = 1 - 2/(exp(2*ALPHA*v)+1); exact in both saturation limits
    float e = __expf(2.0f * ALPHA * v);
    return 1.0f - 2.0f * __frcp_rn(e + 1.0f);
}

// ---------------------------------------------------------------------------
// score: one WARP per node j (src = idx[j]); 8 dims per lane via 2x float4.
//   p1 = tanh(a*e1[src,:]).w[:D]   -> g_row[j]   = (e^{p1+b}, e^{0.2(p1+b)})
//   p2 = tanh(a*e2[src,:]).w[D:]   -> g_col[src] = (e^{p2},   e^{0.2 p2})
// 8 warps/block, 1024 blocks, no __syncthreads, no atomics.
// ---------------------------------------------------------------------------
__global__ void __launch_bounds__(256)
score_kernel(const int* __restrict__ idx,
             const float* __restrict__ e1,
             const float* __restrict__ e2,
             const float* __restrict__ w,
             const float* __restrict__ att_b)
{
    const int warp = (blockIdx.x * 256 + threadIdx.x) >> 5;   // node j
    const int lane = threadIdx.x & 31;
    const int src  = idx[warp];

    const float4* r1 = (const float4*)(e1 + (size_t)src * DIM) + lane * 2;
    const float4* r2 = (const float4*)(e2 + (size_t)src * DIM) + lane * 2;
    const float4* w1 = (const float4*)(w)       + lane * 2;
    const float4* w2 = (const float4*)(w + DIM) + lane * 2;

    float p1 = 0.f, p2 = 0.f;
    #pragma unroll
    for (int q = 0; q < 2; q++) {
        float4 a = r1[q], b = r2[q], wa = __ldg(&w1[q]), wb = __ldg(&w2[q]);
        p1 += fast_tanh_alpha(a.x) * wa.x + fast_tanh_alpha(a.y) * wa.y
            + fast_tanh_alpha(a.z) * wa.z + fast_tanh_alpha(a.w) * wa.w;
        p2 += fast_tanh_alpha(b.x) * wb.x + fast_tanh_alpha(b.y) * wb.y
            + fast_tanh_alpha(b.z) * wb.z + fast_tanh_alpha(b.w) * wb.w;
    }
    #pragma unroll
    for (int o = 16; o > 0; o >>= 1) {
        p1 += __shfl_down_sync(0xffffffffu, p1, o);
        p2 += __shfl_down_sync(0xffffffffu, p2, o);
    }
    if (lane == 0) {
        const float base = p1 + att_b[0];
        g_row[warp] = make_float2(__expf(base), __expf(NEG * base));
        g_col[src]  = make_float2(__expf(p2),   __expf(NEG * p2));
    }
}

// ---------------------------------------------------------------------------
// softmax: one block per row i. 256 threads x 32 cols.
// exp(leaky(base + s2)) == max(eb1*E1[c], eb2*E2[c])  -- EXACT identity
// (leaky(x)=max(x,0.2x), exp monotone). Hot loop: 2 FMUL + 1 FMNMX + 1 FADD
// per element, ZERO transcendentals. g_col (64KB) stays L1-resident.
// ---------------------------------------------------------------------------
__global__ void __launch_bounds__(TPB)
softmax_kernel(float* __restrict__ out)
{
    const int i = blockIdx.x;
    const int t = threadIdx.x;

    const float2 rb  = g_row[i];          // (e^{base}, e^{0.2 base})
    const float4* c4 = (const float4*)g_col;   // entry k = cols {2k, 2k+1}

    float vals[CPT];
    float sum = 0.f;
    #pragma unroll
    for (int q = 0; q < G4; q++) {
        const int g = q * TPB + t;             // group of 4 columns 4g..4g+3
        float4 a = __ldg(&c4[2 * g]);          // (E1,E2, E1,E2) cols 4g,4g+1
        float4 b = __ldg(&c4[2 * g + 1]);      // cols 4g+2, 4g+3
        float v0 = fmaxf(rb.x * a.x, rb.y * a.y);
        float v1 = fmaxf(rb.x * a.z, rb.y * a.w);
        float v2 = fmaxf(rb.x * b.x, rb.y * b.y);
        float v3 = fmaxf(rb.x * b.z, rb.y * b.w);
        vals[q * 4 + 0] = v0;
        vals[q * 4 + 1] = v1;
        vals[q * 4 + 2] = v2;
        vals[q * 4 + 3] = v3;
        sum += (v0 + v1) + (v2 + v3);
    }

    // block sum (8 warps)
    __shared__ float shs[TPB / 32];
    #pragma unroll
    for (int o = 16; o > 0; o >>= 1)
        sum += __shfl_xor_sync(0xffffffffu, sum, o);
    if ((t & 31) == 0) shs[t >> 5] = sum;
    __syncthreads();
    sum = 0.f;
    #pragma unroll
    for (int wgi = 0; wgi < TPB / 32; wgi++) sum += shs[wgi];

    const float inv = __frcp_rn(sum);

    // contiguous STG.128: thread group g covers cols 4g..4g+3
    float4* row4 = (float4*)(out + (size_t)i * NNODES);
    #pragma unroll
    for (int q = 0; q < G4; q++) {
        const int g = q * TPB + t;
        float4 v;
        v.x = vals[q * 4 + 0] * inv;
        v.y = vals[q * 4 + 1] * inv;
        v.z = vals[q * 4 + 2] * inv;
        v.w = vals[q * 4 + 3] * inv;
        row4[g] = v;
    }
}

// ---------------------------------------------------------------------------
// Inputs: idx[int32 N], emb1_w[f32 N*D], emb2_w[f32 N*D], att_w[f32 2D],
//         att_b[f32 1].  Output: f32 N*N.
// ---------------------------------------------------------------------------
extern "C" void kernel_launch(void* const* d_in, const int* in_sizes, int n_in,
                              void* d_out, int out_size)
{
    const int*   idx  = (const int*)  d_in[0];
    const float* e1   = (const float*)d_in[1];
    const float* e2   = (const float*)d_in[2];
    const float* attw = (const float*)d_in[3];
    const float* attb = (const float*)d_in[4];
    float*       out  = (float*)d_out;

    score_kernel<<<NNODES / 8, 256>>>(idx, e1, e2, attw, attb);
    softmax_kernel<<<NNODES, TPB>>>(out);
}

// round 7
// speedup vs baseline: 1.2101x; 1.2101x over previous
#include <cuda_runtime.h>
#include <cuda_bf16.h>
#include <stdint.h>

#define NNODES 8192
#define DIM    256
#define ALPHA  3.0f
#define NEG    0.2f

#define TPB  256                 // softmax threads per block
#define G4   8                   // float4 groups per thread (8*4*256 = 8192)

#define NB        4096           // histogram bins for s2
#define RANGE_LO  (-16.0f)
#define BIN_SCALE (NB / 32.0f)   // bins per unit

// Scratch (__device__ globals; zero-initialized at load, no cudaMalloc)
__device__ float g_s1[NNODES];
__device__ float g_s2p[NNODES];       // permuted: g_s2p[idx[j]] = s2[j]
__device__ float g_binE1[NB];         // Σ e^{s2} per bin      (self-zeroed by scan)
__device__ float g_binE2[NB];         // Σ e^{0.2 s2} per bin  (self-zeroed by scan)
__device__ float g_pre1[NB + 1];      // exclusive prefix of binE1
__device__ float g_pre2[NB + 1];      // exclusive prefix of binE2

__device__ __forceinline__ float fast_tanh_alpha(float v) {
    float e = __expf(2.0f * ALPHA * v);
    return 1.0f - 2.0f * __frcp_rn(e + 1.0f);
}

// ---------------------------------------------------------------------------
// score: one WARP per node j (src = idx[j]).
//   g_s1[j]    = tanh(a*e1[src,:]) . w[:D]
//   g_s2p[src] = p2 = tanh(a*e2[src,:]) . w[D:]
//   bins[bucket(p2)] += (e^{p2}, e^{0.2 p2})    (1 lane, 2 float atomics/node)
// ---------------------------------------------------------------------------
__global__ void __launch_bounds__(256)
score_kernel(const int* __restrict__ idx,
             const float* __restrict__ e1,
             const float* __restrict__ e2,
             const float* __restrict__ w)
{
    const int warp = (blockIdx.x * 256 + threadIdx.x) >> 5;
    const int lane = threadIdx.x & 31;
    const int src  = idx[warp];

    const float4* r1 = (const float4*)(e1 + (size_t)src * DIM) + lane * 2;
    const float4* r2 = (const float4*)(e2 + (size_t)src * DIM) + lane * 2;
    const float4* w1 = (const float4*)(w)       + lane * 2;
    const float4* w2 = (const float4*)(w + DIM) + lane * 2;

    float p1 = 0.f, p2 = 0.f;
    #pragma unroll
    for (int q = 0; q < 2; q++) {
        float4 a = r1[q], b = r2[q], wa = __ldg(&w1[q]), wb = __ldg(&w2[q]);
        p1 += fast_tanh_alpha(a.x) * wa.x + fast_tanh_alpha(a.y) * wa.y
            + fast_tanh_alpha(a.z) * wa.z + fast_tanh_alpha(a.w) * wa.w;
        p2 += fast_tanh_alpha(b.x) * wb.x + fast_tanh_alpha(b.y) * wb.y
            + fast_tanh_alpha(b.z) * wb.z + fast_tanh_alpha(b.w) * wb.w;
    }
    #pragma unroll
    for (int o = 16; o > 0; o >>= 1) {
        p1 += __shfl_down_sync(0xffffffffu, p1, o);
        p2 += __shfl_down_sync(0xffffffffu, p2, o);
    }
    if (lane == 0) {
        g_s1[warp] = p1;
        g_s2p[src] = p2;
        int b = (int)floorf((p2 - RANGE_LO) * BIN_SCALE);
        b = max(0, min(NB - 1, b));
        atomicAdd(&g_binE1[b], __expf(p2));
        atomicAdd(&g_binE2[b], __expf(NEG * p2));
    }
}

// ---------------------------------------------------------------------------
// scan: single block, 1024 threads, 4 bins/thread. Builds exclusive prefix
// sums of both bin arrays, and ZEROES the bins (determinism across replays).
// ---------------------------------------------------------------------------
__global__ void __launch_bounds__(1024)
scan_kernel()
{
    const int t    = threadIdx.x;
    const int lane = t & 31, wrp = t >> 5;
    const int k    = t * 4;

    float a0 = g_binE1[k],   a1 = g_binE1[k+1], a2 = g_binE1[k+2], a3 = g_binE1[k+3];
    float b0 = g_binE2[k],   b1 = g_binE2[k+1], b2 = g_binE2[k+2], b3 = g_binE2[k+3];
    g_binE1[k] = 0.f; g_binE1[k+1] = 0.f; g_binE1[k+2] = 0.f; g_binE1[k+3] = 0.f;
    g_binE2[k] = 0.f; g_binE2[k+1] = 0.f; g_binE2[k+2] = 0.f; g_binE2[k+3] = 0.f;

    float s1 = ((a0 + a1) + (a2 + a3));
    float s2 = ((b0 + b1) + (b2 + b3));

    // warp inclusive scan of per-thread totals
    float i1 = s1, i2 = s2;
    #pragma unroll
    for (int o = 1; o < 32; o <<= 1) {
        float n1 = __shfl_up_sync(0xffffffffu, i1, o);
        float n2 = __shfl_up_sync(0xffffffffu, i2, o);
        if (lane >= o) { i1 += n1; i2 += n2; }
    }
    __shared__ float w1s[32], w2s[32];
    if (lane == 31) { w1s[wrp] = i1; w2s[wrp] = i2; }
    __syncthreads();
    if (wrp == 0) {
        float v1 = w1s[lane], v2 = w2s[lane];
        #pragma unroll
        for (int o = 1; o < 32; o <<= 1) {
            float n1 = __shfl_up_sync(0xffffffffu, v1, o);
            float n2 = __shfl_up_sync(0xffffffffu, v2, o);
            if (lane >= o) { v1 += n1; v2 += n2; }
        }
        w1s[lane] = v1; w2s[lane] = v2;     // inclusive warp totals
    }
    __syncthreads();

    float wb1 = (wrp == 0) ? 0.f : w1s[wrp - 1];
    float wb2 = (wrp == 0) ? 0.f : w2s[wrp - 1];
    float exc1 = wb1 + (i1 - s1);           // exclusive prefix at bin k
    float exc2 = wb2 + (i2 - s2);

    g_pre1[k]   = exc1;            g_pre2[k]   = exc2;
    g_pre1[k+1] = exc1 + a0;       g_pre2[k+1] = exc2 + b0;
    g_pre1[k+2] = exc1 + a0 + a1;  g_pre2[k+2] = exc2 + b0 + b1;
    g_pre1[k+3] = exc1 + a0 + a1 + a2;
    g_pre2[k+3] = exc2 + b0 + b1 + b2;
    if (t == 1023) {
        g_pre1[NB] = exc1 + s1;    // totals
        g_pre2[NB] = exc2 + s2;
    }
}

// ---------------------------------------------------------------------------
// softmax: one block per row i; denominator from prefix tables (O(1)/row),
// then ONE streaming pass: load s2 (32KB, L1-resident), exp(leaky), scale,
// float4 store. No vals array, no mid-kernel reduction.
// ---------------------------------------------------------------------------
__global__ void __launch_bounds__(TPB)
softmax_kernel(const float* __restrict__ att_b,
               float* __restrict__ out)
{
    const int i = blockIdx.x;
    const int t = threadIdx.x;

    __shared__ float sh_base, sh_inv;
    if (t == 0) {
        float base = g_s1[i] + att_b[0];
        // split index: bins [ks, NB) have s2 > -base  -> positive branch
        int ks = (int)floorf((-base - RANGE_LO) * BIN_SCALE) + 1;
        ks = max(0, min(NB, ks));
        float sum = __expf(base)       * (g_pre1[NB] - g_pre1[ks])
                  + __expf(NEG * base) * g_pre2[ks];
        sh_base = base;
        sh_inv  = 1.0f / sum;
    }
    __syncthreads();
    const float base = sh_base;
    const float inv  = sh_inv;

    const float4* c4   = (const float4*)g_s2p;
    float4*       row4 = (float4*)(out + (size_t)i * NNODES);

    #pragma unroll
    for (int q = 0; q < G4; q++) {
        float4 s = __ldg(&c4[q * TPB + t]);
        float x0 = base + s.x, x1 = base + s.y, x2 = base + s.z, x3 = base + s.w;
        float4 v;
        v.x = __expf(fmaxf(x0, NEG * x0)) * inv;
        v.y = __expf(fmaxf(x1, NEG * x1)) * inv;
        v.z = __expf(fmaxf(x2, NEG * x2)) * inv;
        v.w = __expf(fmaxf(x3, NEG * x3)) * inv;
        row4[q * TPB + t] = v;
    }
}

// ---------------------------------------------------------------------------
// Inputs: idx[int32 N], emb1_w[f32 N*D], emb2_w[f32 N*D], att_w[f32 2D],
//         att_b[f32 1].  Output: f32 N*N.
// ---------------------------------------------------------------------------
extern "C" void kernel_launch(void* const* d_in, const int* in_sizes, int n_in,
                              void* d_out, int out_size)
{
    const int*   idx  = (const int*)  d_in[0];
    const float* e1   = (const float*)d_in[1];
    const float* e2   = (const float*)d_in[2];
    const float* attw = (const float*)d_in[3];
    const float* attb = (const float*)d_in[4];
    float*       out  = (float*)d_out;

    score_kernel<<<NNODES / 8, 256>>>(idx, e1, e2, attw);
    scan_kernel<<<1, 1024>>>();
    softmax_kernel<<<NNODES, TPB>>>(attb, out);
}